// round 11
// baseline (speedup 1.0000x reference)
#include <cuda_runtime.h>
#include <cstdint>
#include <cub/cub.cuh>

// Problem constants
#define C_DIM     4096
#define NUMEL     16777216
#define NUMEL_D   16777216.0
#define MAX_K     4500000               // >= S + R = 4,404,019
#define TRIN      393216                // cap for entries in groups >= 3 (~150K expected)
#define M2        1114112               // candidate sort size: R + 64K slack
#define HIST_BINS (1u << 18)            // ordkey >> 13
#define TEMP_BYTES (32u * 1024u * 1024u)

// Static device scratch (allocation-free per harness rules)
__device__ uint32_t g_cnt4[NUMEL / 8];        // packed 4-bit multiplicity, 8MB (L2-resident)
__device__ unsigned long long g_pair[NUMEL];  // epoch-tagged pair rendezvous, 128MB (no memset!)
__device__ uint32_t g_epoch[1];
__device__ uint32_t g_hord[MAX_K];            // dense head ordkeys
__device__ uint32_t g_hkey[MAX_K];            // dense head keys
__device__ uint32_t g_dk[TRIN], g_dk2[TRIN];  // tri keys in/out
__device__ uint32_t g_dp[TRIN], g_dp2[TRIN];  // tri slot payload in/out
__device__ uint32_t g_di[TRIN], g_dv[TRIN];   // tri origidx / value bits (by slot)
__device__ uint32_t g_cord[M2], g_ckey[M2];   // candidates
__device__ uint32_t g_sord[M2], g_skey[M2];   // sorted candidates
__device__ uint32_t g_hist[HIST_BINS];
__device__ uint32_t g_super[1024];
__device__ uint32_t g_B[1];
__device__ uint32_t g_ctrs[4];                // [0]=hcur [1]=tricur [2]=ccur
__device__ unsigned char g_temp[TEMP_BYTES];

static __device__ __forceinline__ uint32_t f32_to_ord(uint32_t b) {
    return b ^ ((uint32_t)((int32_t)b >> 31) | 0x80000000u);
}
static __device__ __forceinline__ uint32_t make_key(const int* __restrict__ samp,
                                                    const int* __restrict__ ridx,
                                                    int S, int i) {
    if (i < S) return (uint32_t)samp[i];
    int r = i - S;
    return (uint32_t)ridx[2 * r] * (uint32_t)C_DIM + (uint32_t)ridx[2 * r + 1];
}

__global__ void epoch_kernel(uint32_t* ep) { ep[0] += 1u; }

__global__ void __launch_bounds__(512) count_kernel(
        const int* __restrict__ samp, const int* __restrict__ ridx,
        int S, int K, uint32_t* __restrict__ cnt4) {
    int i = blockIdx.x * 512 + threadIdx.x;
    if (i >= K) return;
    uint32_t key = make_key(samp, ridx, S, i);
    atomicAdd(&cnt4[key >> 3], 1u << ((key & 7u) * 4u));
}

// c==1: emit head directly. c==2: epoch-tagged atomicExch rendezvous; the
// second arriver emits the (commutative => bit-exact) pair sum. c>=3: append
// to the tiny tri list. All appends block-aggregated.
__global__ void __launch_bounds__(512) classify_kernel(
        const int* __restrict__ samp, const int* __restrict__ ridx,
        const float* __restrict__ grad, const float* __restrict__ rval,
        int S, int K, float adj,
        const uint32_t* __restrict__ cnt4,
        unsigned long long* __restrict__ pairtab,
        const uint32_t* __restrict__ epp,
        uint32_t* __restrict__ ctrs,
        uint32_t* __restrict__ hord, uint32_t* __restrict__ hkey,
        uint32_t* __restrict__ dk, uint32_t* __restrict__ dp,
        uint32_t* __restrict__ di, uint32_t* __restrict__ dv,
        uint32_t* __restrict__ hist) {
    int i = blockIdx.x * 512 + threadIdx.x;
    bool valid = (i < K);
    uint32_t key = 0, bits = 0, c = 0;
    if (valid) {
        key = make_key(samp, ridx, S, i);
        float v = (i < S) ? fabsf(grad[i]) : adj * rval[i - S];
        bits = __float_as_uint(v);
        c = (cnt4[key >> 3] >> ((key & 7u) * 4u)) & 0xFu;
    }

    uint32_t headOrd = 0, headPred = 0;
    if (valid && c == 1u) {
        headOrd = ~f32_to_ord(bits);                    // singleton: sum == value
        headPred = 1u;
    } else if (valid && c == 2u) {
        uint32_t ep = *epp;
        unsigned long long packed = ((unsigned long long)ep << 32) | (unsigned long long)bits;
        unsigned long long old = atomicExch(&pairtab[key], packed);
        if ((uint32_t)(old >> 32) == ep) {              // partner already arrived
            float s = __uint_as_float(bits) + __uint_as_float((uint32_t)old);
            headOrd = ~f32_to_ord(__float_as_uint(s));
            headPred = 1u;
        }
    }
    uint32_t triPred = (valid && c >= 3u) ? 1u : 0u;

    typedef cub::BlockScan<uint32_t, 512> BS;
    __shared__ typename BS::TempStorage ts;
    __shared__ uint32_t s_baseH, s_baseT;

    uint32_t rankH, totH;
    BS(ts).ExclusiveSum(headPred, rankH, totH);
    if (threadIdx.x == 0) s_baseH = (totH > 0) ? atomicAdd(&ctrs[0], totH) : 0u;
    __syncthreads();
    uint32_t rankT, totT;
    BS(ts).ExclusiveSum(triPred, rankT, totT);
    if (threadIdx.x == 0) s_baseT = (totT > 0) ? atomicAdd(&ctrs[1], totT) : 0u;
    __syncthreads();

    if (headPred) {
        uint32_t p = s_baseH + rankH;                   // heads <= K <= MAX_K
        hord[p] = headOrd;
        hkey[p] = key;
        atomicAdd(&hist[headOrd >> 13], 1u);
    }
    if (triPred) {
        uint32_t p = s_baseT + rankT;
        if (p < (uint32_t)TRIN) {
            dk[p] = key; dp[p] = p; di[p] = (uint32_t)i; dv[p] = bits;
        }
    }
}

// Tri list sorted by key (pads keep 0xFFFFFFFF > any 24-bit key). Per group
// head: restore original order via min-origidx selection, sum sequentially
// (bit-exact vs XLA scatter-add), block-append head.
__global__ void __launch_bounds__(256) dupsum_kernel(
        const uint32_t* __restrict__ dk2, const uint32_t* __restrict__ dp2,
        const uint32_t* __restrict__ di,  const uint32_t* __restrict__ dv,
        uint32_t* __restrict__ ctrs, uint32_t* __restrict__ hord,
        uint32_t* __restrict__ hkey, uint32_t* __restrict__ hist) {
    int j = blockIdx.x * 256 + threadIdx.x;
    uint32_t myord = 0, mykey = 0, have = 0;
    if (j < TRIN) {
        uint32_t k = dk2[j];
        if (k <= 0xFFFFFFu) {                              // real 24-bit key (not pad)
            bool head = (j == 0) || (dk2[j - 1] != k);
            if (head) {
                int e = j + 1;
                while (e < TRIN && dk2[e] == k) e++;
                int L = e - j;
                float sum = 0.0f;
                uint32_t lastEx = 0;
                for (int s = 0; s < L; s++) {              // tiny groups (3..~10)
                    uint32_t best = 0xFFFFFFFFu, bv = 0;
                    for (int q = j; q < e; q++) {
                        uint32_t sl = dp2[q];
                        uint32_t oi = di[sl];
                        if (oi >= lastEx && oi < best) { best = oi; bv = dv[sl]; }
                    }
                    sum += __uint_as_float(bv);            // original order => exact
                    lastEx = best + 1u;
                }
                myord = ~f32_to_ord(__float_as_uint(sum));
                mykey = k;
                have = 1;
            }
        }
    }
    typedef cub::BlockScan<uint32_t, 256> BS;
    __shared__ typename BS::TempStorage ts;
    __shared__ uint32_t s_base;
    uint32_t rank, total;
    BS(ts).ExclusiveSum(have, rank, total);
    if (threadIdx.x == 0) s_base = (total > 0) ? atomicAdd(&ctrs[0], total) : 0u;
    __syncthreads();
    if (have) {
        uint32_t p = s_base + rank;
        hord[p] = myord;
        hkey[p] = mykey;
        atomicAdd(&hist[myord >> 13], 1u);
    }
}

__global__ void coarse_kernel(const uint32_t* __restrict__ hist,
                              uint32_t* __restrict__ super) {
    typedef cub::BlockReduce<uint32_t, 256> BR;
    __shared__ typename BR::TempStorage ts;
    uint32_t v = hist[blockIdx.x * 256 + threadIdx.x];
    uint32_t s = BR(ts).Sum(v);
    if (threadIdx.x == 0) super[blockIdx.x] = s;
}

// Single block: smallest bin boundary B with #heads{ordkey < B} >= R.
__global__ void select_kernel(const uint32_t* __restrict__ super,
                              const uint32_t* __restrict__ hist,
                              uint32_t R, uint32_t* __restrict__ Bout) {
    typedef cub::BlockScan<uint32_t, 1024> BS;
    __shared__ typename BS::TempStorage ts;
    __shared__ uint32_t s_sb, s_base2;
    if (threadIdx.x == 0) { s_sb = 0xFFFFFFFFu; s_base2 = 0; }
    __syncthreads();
    uint32_t v = super[threadIdx.x];
    uint32_t inc;
    BS(ts).InclusiveSum(v, inc);
    if (inc >= R && (inc - v) < R) { s_sb = threadIdx.x; s_base2 = inc - v; }
    __syncthreads();
    if (s_sb == 0xFFFFFFFFu) {
        if (threadIdx.x == 0) Bout[0] = 0xFFFFFFFFu;
        return;
    }
    uint32_t sb = s_sb, base = s_base2;
    __syncthreads();
    uint32_t h = (threadIdx.x < 256) ? hist[sb * 256 + threadIdx.x] : 0u;
    uint32_t inc1;
    BS(ts).InclusiveSum(h, inc1);
    if (threadIdx.x < 256) {
        uint32_t excl = inc1 - h;
        if (base + inc1 >= R && base + excl < R)
            Bout[0] = ((sb * 256u + threadIdx.x) + 1u) << 13;
    }
}

// Block-aggregated candidate append over the dense head list.
__global__ void __launch_bounds__(512) filter_kernel(
        const uint32_t* __restrict__ hord, const uint32_t* __restrict__ hkey,
        const uint32_t* __restrict__ ctrs, const uint32_t* __restrict__ Bp,
        uint32_t* __restrict__ ccur,
        uint32_t* __restrict__ cord, uint32_t* __restrict__ ckey) {
    int j = blockIdx.x * 512 + threadIdx.x;
    uint32_t H = ctrs[0];
    uint32_t B = *Bp;
    uint32_t x = (j < (int)H) ? hord[j] : 0xFFFFFFFFu;
    uint32_t pred = (x < B) ? 1u : 0u;
    typedef cub::BlockScan<uint32_t, 512> BS;
    __shared__ typename BS::TempStorage ts;
    __shared__ uint32_t s_base;
    uint32_t rank, total;
    BS(ts).ExclusiveSum(pred, rank, total);
    if (threadIdx.x == 0) s_base = (total > 0) ? atomicAdd(ccur, total) : 0u;
    __syncthreads();
    if (pred) {
        uint32_t p = s_base + rank;
        if (p < (uint32_t)M2) {
            cord[p] = x;
            ckey[p] = hkey[j];
        }
    }
}

// Ascending key within each equal-ordkey run => exact lax.top_k tie-break.
__global__ void tiefix_kernel(const uint32_t* __restrict__ sord,
                              uint32_t* __restrict__ skey) {
    int j = blockIdx.x * blockDim.x + threadIdx.x;
    if (j >= M2) return;
    uint32_t o = sord[j];
    if (o == 0xFFFFFFFFu) return;                    // pad
    if (j > 0 && sord[j - 1] == o) return;           // not run start
    if (j + 1 >= M2 || sord[j + 1] != o) return;     // run length 1
    int e = j + 1;
    while (e < M2 && sord[e] == o) e++;
    for (int a = j + 1; a < e; a++) {
        uint32_t kx = skey[a];
        int t = a;
        while (t > j && skey[t - 1] > kx) { skey[t] = skey[t - 1]; t--; }
        skey[t] = kx;
    }
}

__global__ void output_kernel(const uint32_t* __restrict__ sord,
                              const uint32_t* __restrict__ skey,
                              int R, int write_idx, int write_val, int val_off,
                              float* __restrict__ out) {
    int r = blockIdx.x * blockDim.x + threadIdx.x;
    if (r >= R) return;
    uint32_t key = skey[r];
    if (write_idx) {
        out[2 * r]     = (float)(key >> 12);
        out[2 * r + 1] = (float)(key & 4095u);
    }
    if (write_val) {
        uint32_t u = ~sord[r];
        uint32_t b = (u & 0x80000000u) ? (u ^ 0x80000000u) : ~u;
        out[val_off + r] = __uint_as_float(b);
    }
}

extern "C" void kernel_launch(void* const* d_in, const int* in_sizes, int n_in,
                              void* d_out, int out_size) {
    (void)n_in;
    const int*   samp = (const int*)d_in[0];
    const int*   ridx = (const int*)d_in[1];
    const float* rval = (const float*)d_in[2];
    const float* grad = (const float*)d_in[3];

    int S = in_sizes[0];
    int R = in_sizes[2];
    int K = S + R;
    if (K > MAX_K) K = MAX_K;

    double frac = (double)S / NUMEL_D;
    float adj = (float)(1.0 - frac * (1.0 - 0.95));

    uint32_t *cnt4, *ep, *hord, *hkey, *dk, *dk2, *dp, *dp2, *di, *dv;
    uint32_t *cord, *ckey, *sord, *skey, *hist, *super, *Bp, *ctrs;
    unsigned long long* pairtab;
    void* tmp;
    cudaGetSymbolAddress((void**)&cnt4, g_cnt4);
    cudaGetSymbolAddress((void**)&pairtab, g_pair);
    cudaGetSymbolAddress((void**)&ep,   g_epoch);
    cudaGetSymbolAddress((void**)&hord, g_hord);
    cudaGetSymbolAddress((void**)&hkey, g_hkey);
    cudaGetSymbolAddress((void**)&dk,   g_dk);
    cudaGetSymbolAddress((void**)&dk2,  g_dk2);
    cudaGetSymbolAddress((void**)&dp,   g_dp);
    cudaGetSymbolAddress((void**)&dp2,  g_dp2);
    cudaGetSymbolAddress((void**)&di,   g_di);
    cudaGetSymbolAddress((void**)&dv,   g_dv);
    cudaGetSymbolAddress((void**)&cord, g_cord);
    cudaGetSymbolAddress((void**)&ckey, g_ckey);
    cudaGetSymbolAddress((void**)&sord, g_sord);
    cudaGetSymbolAddress((void**)&skey, g_skey);
    cudaGetSymbolAddress((void**)&hist, g_hist);
    cudaGetSymbolAddress((void**)&super,g_super);
    cudaGetSymbolAddress((void**)&Bp,   g_B);
    cudaGetSymbolAddress((void**)&ctrs, g_ctrs);
    cudaGetSymbolAddress(&tmp, g_temp);
    const size_t TMPB = (size_t)TEMP_BYTES;

    const int BLK = 256;
    const int GK512 = (K + 511) / 512;

    // per-replay re-init (small; pair table needs NONE thanks to epoch tags)
    cudaMemsetAsync(cnt4, 0,    (size_t)(NUMEL / 8) * sizeof(uint32_t)); // 8MB
    cudaMemsetAsync(hist, 0,    HIST_BINS * sizeof(uint32_t));           // 1MB
    cudaMemsetAsync(ctrs, 0,    4 * sizeof(uint32_t));
    cudaMemsetAsync(dk,   0xFF, (size_t)TRIN * sizeof(uint32_t));        // 1.5MB
    cudaMemsetAsync(cord, 0xFF, (size_t)M2 * sizeof(uint32_t));          // 4.3MB
    epoch_kernel<<<1, 1>>>(ep);

    // 1) 4-bit multiplicity per key (L2-resident)
    count_kernel<<<GK512, 512>>>(samp, ridx, S, K, cnt4);

    // 2) classify: singles + pairs resolved inline, >=3 to tri list
    classify_kernel<<<GK512, 512>>>(samp, ridx, grad, rval, S, K, adj,
                                    cnt4, pairtab, ep, ctrs,
                                    hord, hkey, dk, dp, di, dv, hist);

    // 3) sort tri entries by key, restore order, emit group heads
    {
        size_t need = 0;
        cub::DeviceRadixSort::SortPairs(nullptr, need, dk, dk2, dp, dp2, TRIN, 0, 32);
        if (need <= TMPB)
            cub::DeviceRadixSort::SortPairs(tmp, need, dk, dk2, dp, dp2, TRIN, 0, 32);
    }
    dupsum_kernel<<<(TRIN + BLK - 1) / BLK, BLK>>>(dk2, dp2, di, dv,
                                                   ctrs, hord, hkey, hist);

    // 4) threshold B (bin-granular, keeps all ties of the R-th element)
    coarse_kernel<<<1024, 256>>>(hist, super);
    select_kernel<<<1, 1024>>>(super, hist, (uint32_t)R, Bp);

    // 5) candidate filter over dense heads (block-aggregated append)
    filter_kernel<<<(MAX_K + 511) / 512, 512>>>(hord, hkey, ctrs, Bp,
                                                &ctrs[2], cord, ckey);

    // 6) sort candidates by ordkey
    {
        size_t need = 0;
        cub::DeviceRadixSort::SortPairs(nullptr, need, cord, sord, ckey, skey, M2, 0, 32);
        if (need <= TMPB)
            cub::DeviceRadixSort::SortPairs(tmp, need, cord, sord, ckey, skey, M2, 0, 32);
    }

    // 7) exact tie-break: ascending key within each equal-value run
    tiefix_kernel<<<(M2 + BLK - 1) / BLK, BLK>>>(sord, skey);

    // 8) emit [new_index (R,2), top_vals (R)] as f32
    int write_idx = 1, write_val = 1, val_off = 2 * R;
    if (out_size == R)          { write_idx = 0; val_off = 0; }
    else if (out_size == 2 * R) { write_val = 0; }
    output_kernel<<<(R + BLK - 1) / BLK, BLK>>>(sord, skey, R,
                                                write_idx, write_val, val_off,
                                                (float*)d_out);
}

// round 12
// speedup vs baseline: 1.0341x; 1.0341x over previous
#include <cuda_runtime.h>
#include <cstdint>
#include <cub/cub.cuh>

// Problem constants
#define C_DIM     4096
#define NUMEL_D   16777216.0
#define MAX_K     4500000               // >= S + R = 4,404,019
#define M_SORT    1114112               // candidate sort size: R + 64K slack
#define HIST_BINS (1u << 18)            // ordkey >> 13
#define TEMP_BYTES (96u * 1024u * 1024u)

// Static device scratch (allocation-free per harness rules)
__device__ uint32_t g_ka[MAX_K];   // pack keys -> scan out
__device__ uint32_t g_kb[MAX_K];   // sort1 key out (key-sorted keys)
__device__ uint32_t g_va[MAX_K];   // pack value bits
__device__ uint32_t g_vb[MAX_K];   // sort1 value out (key-ordered value bits) -> flags
__device__ uint32_t g_w [MAX_K];   // per-position ordkey (heads real, non-heads 0xFFFFFFFF)
__device__ uint32_t g_cord[M_SORT], g_ckey[M_SORT];   // candidates
__device__ uint32_t g_sord[M_SORT], g_skey[M_SORT];   // sorted candidates
__device__ uint32_t g_hist[HIST_BINS];
__device__ uint32_t g_super[1024];
__device__ uint32_t g_B[1];
__device__ unsigned char g_temp[TEMP_BYTES];

static __device__ __forceinline__ uint32_t f32_to_ord(uint32_t b) {
    return b ^ ((uint32_t)((int32_t)b >> 31) | 0x80000000u);
}

__global__ void pack_kernel(const int* __restrict__ samp,
                            const int* __restrict__ ridx,
                            const float* __restrict__ grad,
                            const float* __restrict__ rval,
                            int S, int K, float adj,
                            uint32_t* __restrict__ keys,
                            uint32_t* __restrict__ vals) {
    int i = blockIdx.x * blockDim.x + threadIdx.x;
    if (i >= K) return;
    uint32_t key; float v;
    if (i < S) {
        key = (uint32_t)samp[i];
        v = fabsf(grad[i]);
    } else {
        int r = i - S;
        key = (uint32_t)ridx[2 * r] * (uint32_t)C_DIM + (uint32_t)ridx[2 * r + 1];
        v = adj * rval[r];
    }
    keys[i] = key;
    vals[i] = __float_as_uint(v);
}

// Per segment-head: sum values sequentially (stable sort1 => original order),
// emit ~ord(sum); non-heads 0xFFFFFFFF. Histogram heads for threshold pick.
__global__ void headsum_kernel(const uint32_t* __restrict__ skeys,
                               const uint32_t* __restrict__ svals,
                               int K,
                               uint32_t* __restrict__ out_ord,
                               uint32_t* __restrict__ hist) {
    int j = blockIdx.x * blockDim.x + threadIdx.x;
    if (j >= K) return;
    uint32_t key = skeys[j];
    bool head = (j == 0) || (skeys[j - 1] != key);
    if (!head) {
        out_ord[j] = 0xFFFFFFFFu;
        return;
    }
    float sum = 0.0f;
    int t = j;
    while (t < K && skeys[t] == key) {
        sum += __uint_as_float(svals[t]);   // sequential, matches XLA scatter-add order
        ++t;
    }
    uint32_t ordk = ~f32_to_ord(__float_as_uint(sum));  // <= 0x7FFFFFFF (sum >= 0)
    out_ord[j] = ordk;
    atomicAdd(&hist[ordk >> 13], 1u);
}

__global__ void coarse_kernel(const uint32_t* __restrict__ hist,
                              uint32_t* __restrict__ super) {
    typedef cub::BlockReduce<uint32_t, 256> BR;
    __shared__ typename BR::TempStorage ts;
    uint32_t v = hist[blockIdx.x * 256 + threadIdx.x];
    uint32_t s = BR(ts).Sum(v);
    if (threadIdx.x == 0) super[blockIdx.x] = s;
}

// Single block: smallest bin boundary B with #heads{ordkey < B} >= R.
__global__ void select_kernel(const uint32_t* __restrict__ super,
                              const uint32_t* __restrict__ hist,
                              uint32_t R, uint32_t* __restrict__ Bout) {
    typedef cub::BlockScan<uint32_t, 1024> BS;
    __shared__ typename BS::TempStorage ts;
    __shared__ uint32_t s_sb, s_base2;
    if (threadIdx.x == 0) { s_sb = 0xFFFFFFFFu; s_base2 = 0; }
    __syncthreads();
    uint32_t v = super[threadIdx.x];
    uint32_t inc;
    BS(ts).InclusiveSum(v, inc);
    if (inc >= R && (inc - v) < R) { s_sb = threadIdx.x; s_base2 = inc - v; }
    __syncthreads();
    if (s_sb == 0xFFFFFFFFu) {                // pathological: fewer heads than R
        if (threadIdx.x == 0) Bout[0] = 0xFFFFFFFFu;
        return;
    }
    uint32_t sb = s_sb, base = s_base2;
    __syncthreads();                          // before TempStorage reuse
    uint32_t h = (threadIdx.x < 256) ? hist[sb * 256 + threadIdx.x] : 0u;
    uint32_t inc1;
    BS(ts).InclusiveSum(h, inc1);
    if (threadIdx.x < 256) {
        uint32_t excl = inc1 - h;
        if (base + inc1 >= R && base + excl < R)
            Bout[0] = ((sb * 256u + threadIdx.x) + 1u) << 13;
    }
}

__global__ void flags_kernel(const uint32_t* __restrict__ ordk,
                             const uint32_t* __restrict__ Bp,
                             int K,
                             uint32_t* __restrict__ flags) {
    int j = blockIdx.x * blockDim.x + threadIdx.x;
    if (j >= K) return;
    flags[j] = (ordk[j] < *Bp) ? 1u : 0u;
}

__global__ void compact_kernel(const uint32_t* __restrict__ ordk,
                               const uint32_t* __restrict__ scan,
                               const uint32_t* __restrict__ skeys,
                               const uint32_t* __restrict__ Bp,
                               int K,
                               uint32_t* __restrict__ cand_ord,
                               uint32_t* __restrict__ cand_key) {
    int j = blockIdx.x * blockDim.x + threadIdx.x;
    if (j >= K) return;
    uint32_t x = ordk[j];
    if (x < *Bp) {
        uint32_t p = scan[j];
        if (p < (uint32_t)M_SORT) {
            cand_ord[p] = x;
            cand_key[p] = skeys[j];
        }
    }
}

__global__ void output_kernel(const uint32_t* __restrict__ sord,
                              const uint32_t* __restrict__ skey,
                              int R, int write_idx, int write_val, int val_off,
                              float* __restrict__ out) {
    int r = blockIdx.x * blockDim.x + threadIdx.x;
    if (r >= R) return;
    uint32_t key = skey[r];
    if (write_idx) {
        out[2 * r]     = (float)(key >> 12);
        out[2 * r + 1] = (float)(key & 4095u);
    }
    if (write_val) {
        uint32_t u = ~sord[r];
        uint32_t b = (u & 0x80000000u) ? (u ^ 0x80000000u) : ~u;
        out[val_off + r] = __uint_as_float(b);
    }
}

extern "C" void kernel_launch(void* const* d_in, const int* in_sizes, int n_in,
                              void* d_out, int out_size) {
    (void)n_in;
    const int*   samp = (const int*)d_in[0];
    const int*   ridx = (const int*)d_in[1];
    const float* rval = (const float*)d_in[2];
    const float* grad = (const float*)d_in[3];

    int S = in_sizes[0];
    int R = in_sizes[2];
    int K = S + R;
    if (K > MAX_K) K = MAX_K;

    double frac = (double)S / NUMEL_D;
    float adj = (float)(1.0 - frac * (1.0 - 0.95));

    uint32_t *ka, *kb, *va, *vb, *w;
    uint32_t *cord, *ckey, *sord, *skey, *hist, *super, *Bp;
    void* tmp;
    cudaGetSymbolAddress((void**)&ka, g_ka);
    cudaGetSymbolAddress((void**)&kb, g_kb);
    cudaGetSymbolAddress((void**)&va, g_va);
    cudaGetSymbolAddress((void**)&vb, g_vb);
    cudaGetSymbolAddress((void**)&w,  g_w);
    cudaGetSymbolAddress((void**)&cord, g_cord);
    cudaGetSymbolAddress((void**)&ckey, g_ckey);
    cudaGetSymbolAddress((void**)&sord, g_sord);
    cudaGetSymbolAddress((void**)&skey, g_skey);
    cudaGetSymbolAddress((void**)&hist, g_hist);
    cudaGetSymbolAddress((void**)&super, g_super);
    cudaGetSymbolAddress((void**)&Bp, g_B);
    cudaGetSymbolAddress(&tmp, g_temp);
    const size_t TMPB = (size_t)TEMP_BYTES;

    const int BLK = 256;
    const int GK = (K + BLK - 1) / BLK;

    // per-replay re-init
    cudaMemsetAsync(hist, 0, HIST_BINS * sizeof(uint32_t));       // 1MB
    cudaMemsetAsync(cord, 0xFF, (size_t)M_SORT * sizeof(uint32_t)); // pads sort last

    // 1) Build (key, value-bits)
    pack_kernel<<<GK, BLK>>>(samp, ridx, grad, rval, S, K, adj, ka, va);

    // 2) Stable sort by 24-bit key, payload = value bits (original order per key kept)
    {
        size_t need = 0;
        cub::DeviceRadixSort::SortPairs(nullptr, need, ka, kb, va, vb, K, 0, 24);
        if (need <= TMPB)
            cub::DeviceRadixSort::SortPairs(tmp, need, ka, kb, va, vb, K, 0, 24);
    }

    // 3) Ordered per-segment sums -> head ordkeys + histogram
    headsum_kernel<<<GK, BLK>>>(kb, vb, K, w, hist);

    // 4) Threshold B (bin-granular, keeps all ties of the R-th element)
    coarse_kernel<<<1024, 256>>>(hist, super);
    select_kernel<<<1, 1024>>>(super, hist, (uint32_t)R, Bp);

    // 5) Order-preserving compaction of candidates (ascending-key order retained)
    //    flags into vb (dead after headsum), scan into ka (dead after sort1)
    flags_kernel<<<GK, BLK>>>(w, Bp, K, vb);
    {
        size_t need = 0;
        cub::DeviceScan::ExclusiveSum(nullptr, need, vb, ka, K);
        if (need <= TMPB)
            cub::DeviceScan::ExclusiveSum(tmp, need, vb, ka, K);
    }
    compact_kernel<<<GK, BLK>>>(w, ka, kb, Bp, K, cord, ckey);

    // 6) Stable pair sort: ascending ordkey == (value desc, key asc)
    {
        size_t need = 0;
        cub::DeviceRadixSort::SortPairs(nullptr, need, cord, sord, ckey, skey,
                                        M_SORT, 0, 32);
        if (need <= TMPB)
            cub::DeviceRadixSort::SortPairs(tmp, need, cord, sord, ckey, skey,
                                            M_SORT, 0, 32);
    }

    // 7) Emit [new_index (R,2), top_vals (R)] as f32
    int write_idx = 1, write_val = 1, val_off = 2 * R;
    if (out_size == R)          { write_idx = 0; val_off = 0; }
    else if (out_size == 2 * R) { write_val = 0; }
    output_kernel<<<(R + BLK - 1) / BLK, BLK>>>(sord, skey, R,
                                                write_idx, write_val, val_off,
                                                (float*)d_out);
}

// round 13
// speedup vs baseline: 1.1147x; 1.0780x over previous
#include <cuda_runtime.h>
#include <cstdint>
#include <cub/cub.cuh>

// Problem constants
#define C_DIM     4096
#define NUMEL     16777216
#define W4        (NUMEL / 4)           // 4,194,304 count words
#define NUMEL_D   16777216.0
#define MAX_K     4500000               // >= S + R = 4,404,019
#define M2        1114112               // candidate sort size: R + 64K slack
#define HIST_BINS (1u << 18)            // ordkey >> 13
#define TEMP_BYTES (32u * 1024u * 1024u)

// Static device scratch (allocation-free per harness rules)
__device__ uint32_t g_cnt[W4];                 // per-key count (low nibble) + cursor (high nibble), 16MB
__device__ uint32_t g_sums[W4];                // per-word totals
__device__ uint32_t g_base[W4];                // exclusive scan of totals
__device__ unsigned long long g_z[MAX_K];      // key-grouped (origidx<<32)|valbits
__device__ uint32_t g_hord[MAX_K];             // dense head ordkeys
__device__ uint32_t g_hkey[MAX_K];             // dense head keys
__device__ uint32_t g_cord[M2], g_ckey[M2];    // candidates
__device__ uint32_t g_sord[M2], g_skey[M2];    // sorted candidates
__device__ uint32_t g_hist[HIST_BINS + 4];     // histogram + [HIST_BINS]=hcur, [HIST_BINS+1]=ccur
__device__ uint32_t g_super[1024];
__device__ uint32_t g_B[1];
__device__ unsigned char g_temp[TEMP_BYTES];

static __device__ __forceinline__ uint32_t f32_to_ord(uint32_t b) {
    return b ^ ((uint32_t)((int32_t)b >> 31) | 0x80000000u);
}
static __device__ __forceinline__ uint32_t make_key(const int* __restrict__ samp,
                                                    const int* __restrict__ ridx,
                                                    int S, int i) {
    if (i < S) return (uint32_t)samp[i];
    int r = i - S;
    return (uint32_t)ridx[2 * r] * (uint32_t)C_DIM + (uint32_t)ridx[2 * r + 1];
}

__global__ void __launch_bounds__(512) count_kernel(
        const int* __restrict__ samp, const int* __restrict__ ridx,
        int S, int K, uint32_t* __restrict__ cnt) {
    int i = blockIdx.x * 512 + threadIdx.x;
    if (i >= K) return;
    uint32_t key = make_key(samp, ridx, S, i);
    atomicAdd(&cnt[key >> 2], 1u << ((key & 3u) * 8u));   // low nibble of its byte
}

__global__ void __launch_bounds__(512) sums_kernel(
        const uint32_t* __restrict__ cnt, uint32_t* __restrict__ sums) {
    int w = blockIdx.x * 512 + threadIdx.x;
    if (w >= W4) return;
    uint32_t c = cnt[w];
    uint32_t p = (c & 0x00FF00FFu) + ((c >> 8) & 0x00FF00FFu);
    sums[w] = (p & 0xFFFFu) + (p >> 16);
}

// dest = base[word] + (counts of lanes below) + intra-key rank.
// Rank comes from the cursor high-nibble of the SAME count byte (atomicAdd 0x10).
__global__ void __launch_bounds__(512) scatter_kernel(
        const int* __restrict__ samp, const int* __restrict__ ridx,
        const float* __restrict__ grad, const float* __restrict__ rval,
        int S, int K, float adj,
        uint32_t* __restrict__ cnt, const uint32_t* __restrict__ base,
        unsigned long long* __restrict__ z) {
    int i = blockIdx.x * 512 + threadIdx.x;
    if (i >= K) return;
    uint32_t key = make_key(samp, ridx, S, i);
    float v = (i < S) ? fabsf(grad[i]) : adj * rval[i - S];
    uint32_t w = key >> 2, lane = key & 3u;
    uint32_t old = atomicAdd(&cnt[w], 0x10u << (lane * 8u));
    uint32_t rank = (old >> (lane * 8u + 4u)) & 0xFu;
    uint32_t below = 0;
    #pragma unroll
    for (uint32_t b = 0; b < 3; b++)
        if (b < lane) below += (old >> (b * 8u)) & 0xFu;
    uint32_t dest = base[w] + below + rank;
    z[dest] = ((unsigned long long)(uint32_t)i << 32) | (unsigned long long)__float_as_uint(v);
}

// One thread per word: its 4 key-groups are CONTIGUOUS at base[w].
// Sort each tiny group by origidx (canonical order; bit-exact sums), emit heads.
__global__ void __launch_bounds__(256) headsum2_kernel(
        const uint32_t* __restrict__ cnt, const uint32_t* __restrict__ base,
        const unsigned long long* __restrict__ z,
        uint32_t* __restrict__ hcur,
        uint32_t* __restrict__ hord, uint32_t* __restrict__ hkey,
        uint32_t* __restrict__ hist) {
    int w = blockIdx.x * 256 + threadIdx.x;
    uint32_t nheads = 0;
    uint32_t lord[4], lkey[4];
    if (w < W4) {
        uint32_t c = cnt[w];
        uint32_t b = base[w];
        #pragma unroll
        for (uint32_t lane = 0; lane < 4; lane++) {
            uint32_t n = (c >> (lane * 8u)) & 0xFu;
            if (n == 0) continue;
            unsigned long long buf[15];
            for (uint32_t q = 0; q < n; q++) buf[q] = z[b + q];
            // insertion sort by origidx (high 32) -> exact concat order
            for (uint32_t a = 1; a < n; a++) {
                unsigned long long x = buf[a];
                int t = (int)a;
                while (t > 0 && buf[t - 1] > x) { buf[t] = buf[t - 1]; t--; }
                buf[t] = x;
            }
            float sum = 0.0f;
            for (uint32_t q = 0; q < n; q++)
                sum += __uint_as_float((uint32_t)buf[q]);
            lord[nheads] = ~f32_to_ord(__float_as_uint(sum));
            lkey[nheads] = ((uint32_t)w << 2) | lane;
            nheads++;
            b += n;
        }
    }
    typedef cub::BlockScan<uint32_t, 256> BS;
    __shared__ typename BS::TempStorage ts;
    __shared__ uint32_t s_base;
    uint32_t rank, total;
    BS(ts).ExclusiveSum(nheads, rank, total);
    if (threadIdx.x == 0) s_base = (total > 0) ? atomicAdd(hcur, total) : 0u;
    __syncthreads();
    uint32_t p = s_base + rank;
    for (uint32_t h = 0; h < nheads; h++) {
        hord[p + h] = lord[h];
        hkey[p + h] = lkey[h];
        atomicAdd(&hist[lord[h] >> 13], 1u);
    }
}

__global__ void coarse_kernel(const uint32_t* __restrict__ hist,
                              uint32_t* __restrict__ super) {
    typedef cub::BlockReduce<uint32_t, 256> BR;
    __shared__ typename BR::TempStorage ts;
    uint32_t v = hist[blockIdx.x * 256 + threadIdx.x];
    uint32_t s = BR(ts).Sum(v);
    if (threadIdx.x == 0) super[blockIdx.x] = s;
}

// Single block: smallest bin boundary B with #heads{ordkey < B} >= R.
__global__ void select_kernel(const uint32_t* __restrict__ super,
                              const uint32_t* __restrict__ hist,
                              uint32_t R, uint32_t* __restrict__ Bout) {
    typedef cub::BlockScan<uint32_t, 1024> BS;
    __shared__ typename BS::TempStorage ts;
    __shared__ uint32_t s_sb, s_base2;
    if (threadIdx.x == 0) { s_sb = 0xFFFFFFFFu; s_base2 = 0; }
    __syncthreads();
    uint32_t v = super[threadIdx.x];
    uint32_t inc;
    BS(ts).InclusiveSum(v, inc);
    if (inc >= R && (inc - v) < R) { s_sb = threadIdx.x; s_base2 = inc - v; }
    __syncthreads();
    if (s_sb == 0xFFFFFFFFu) {
        if (threadIdx.x == 0) Bout[0] = 0xFFFFFFFFu;
        return;
    }
    uint32_t sb = s_sb, base = s_base2;
    __syncthreads();
    uint32_t h = (threadIdx.x < 256) ? hist[sb * 256 + threadIdx.x] : 0u;
    uint32_t inc1;
    BS(ts).InclusiveSum(h, inc1);
    if (threadIdx.x < 256) {
        uint32_t excl = inc1 - h;
        if (base + inc1 >= R && base + excl < R)
            Bout[0] = ((sb * 256u + threadIdx.x) + 1u) << 13;
    }
}

// Block-aggregated candidate append over the dense head list.
__global__ void __launch_bounds__(512) filter_kernel(
        const uint32_t* __restrict__ hord, const uint32_t* __restrict__ hkey,
        const uint32_t* __restrict__ hcurp, const uint32_t* __restrict__ Bp,
        uint32_t* __restrict__ ccur,
        uint32_t* __restrict__ cord, uint32_t* __restrict__ ckey) {
    int j = blockIdx.x * 512 + threadIdx.x;
    uint32_t H = *hcurp;
    uint32_t B = *Bp;
    uint32_t x = (j < (int)H) ? hord[j] : 0xFFFFFFFFu;
    uint32_t pred = (x < B) ? 1u : 0u;
    typedef cub::BlockScan<uint32_t, 512> BS;
    __shared__ typename BS::TempStorage ts;
    __shared__ uint32_t s_base;
    uint32_t rank, total;
    BS(ts).ExclusiveSum(pred, rank, total);
    if (threadIdx.x == 0) s_base = (total > 0) ? atomicAdd(ccur, total) : 0u;
    __syncthreads();
    if (pred) {
        uint32_t p = s_base + rank;
        if (p < (uint32_t)M2) {
            cord[p] = x;
            ckey[p] = hkey[j];
        }
    }
}

// Ascending key within each equal-ordkey run => exact lax.top_k tie-break.
__global__ void tiefix_kernel(const uint32_t* __restrict__ sord,
                              uint32_t* __restrict__ skey) {
    int j = blockIdx.x * blockDim.x + threadIdx.x;
    if (j >= M2) return;
    uint32_t o = sord[j];
    if (o == 0xFFFFFFFFu) return;                    // pad
    if (j > 0 && sord[j - 1] == o) return;           // not run start
    if (j + 1 >= M2 || sord[j + 1] != o) return;     // run length 1
    int e = j + 1;
    while (e < M2 && sord[e] == o) e++;
    for (int a = j + 1; a < e; a++) {
        uint32_t kx = skey[a];
        int t = a;
        while (t > j && skey[t - 1] > kx) { skey[t] = skey[t - 1]; t--; }
        skey[t] = kx;
    }
}

__global__ void output_kernel(const uint32_t* __restrict__ sord,
                              const uint32_t* __restrict__ skey,
                              int R, int write_idx, int write_val, int val_off,
                              float* __restrict__ out) {
    int r = blockIdx.x * blockDim.x + threadIdx.x;
    if (r >= R) return;
    uint32_t key = skey[r];
    if (write_idx) {
        out[2 * r]     = (float)(key >> 12);
        out[2 * r + 1] = (float)(key & 4095u);
    }
    if (write_val) {
        uint32_t u = ~sord[r];
        uint32_t b = (u & 0x80000000u) ? (u ^ 0x80000000u) : ~u;
        out[val_off + r] = __uint_as_float(b);
    }
}

extern "C" void kernel_launch(void* const* d_in, const int* in_sizes, int n_in,
                              void* d_out, int out_size) {
    (void)n_in;
    const int*   samp = (const int*)d_in[0];
    const int*   ridx = (const int*)d_in[1];
    const float* rval = (const float*)d_in[2];
    const float* grad = (const float*)d_in[3];

    int S = in_sizes[0];
    int R = in_sizes[2];
    int K = S + R;
    if (K > MAX_K) K = MAX_K;

    double frac = (double)S / NUMEL_D;
    float adj = (float)(1.0 - frac * (1.0 - 0.95));

    uint32_t *cnt, *sums, *base, *hord, *hkey;
    uint32_t *cord, *ckey, *sord, *skey, *hist, *super, *Bp;
    unsigned long long* z;
    void* tmp;
    cudaGetSymbolAddress((void**)&cnt,  g_cnt);
    cudaGetSymbolAddress((void**)&sums, g_sums);
    cudaGetSymbolAddress((void**)&base, g_base);
    cudaGetSymbolAddress((void**)&z,    g_z);
    cudaGetSymbolAddress((void**)&hord, g_hord);
    cudaGetSymbolAddress((void**)&hkey, g_hkey);
    cudaGetSymbolAddress((void**)&cord, g_cord);
    cudaGetSymbolAddress((void**)&ckey, g_ckey);
    cudaGetSymbolAddress((void**)&sord, g_sord);
    cudaGetSymbolAddress((void**)&skey, g_skey);
    cudaGetSymbolAddress((void**)&hist, g_hist);
    cudaGetSymbolAddress((void**)&super,g_super);
    cudaGetSymbolAddress((void**)&Bp,   g_B);
    cudaGetSymbolAddress(&tmp, g_temp);
    const size_t TMPB = (size_t)TEMP_BYTES;

    uint32_t* hcur = hist + HIST_BINS;
    uint32_t* ccur = hist + HIST_BINS + 1;

    const int BLK = 256;
    const int GK512 = (K + 511) / 512;
    const int GW512 = (W4 + 511) / 512;

    // per-replay re-init
    cudaMemsetAsync(cnt,  0,    (size_t)W4 * sizeof(uint32_t));            // 16MB
    cudaMemsetAsync(hist, 0,    (HIST_BINS + 4) * sizeof(uint32_t));       // 1MB (covers hcur/ccur)
    cudaMemsetAsync(cord, 0xFF, (size_t)M2 * sizeof(uint32_t));            // pads sort last

    // 1) per-key multiplicity (count nibble)
    count_kernel<<<GK512, 512>>>(samp, ridx, S, K, cnt);

    // 2) per-word totals + exclusive scan -> group base offsets
    sums_kernel<<<GW512, 512>>>(cnt, sums);
    {
        size_t need = 0;
        cub::DeviceScan::ExclusiveSum(nullptr, need, sums, base, W4);
        if (need <= TMPB)
            cub::DeviceScan::ExclusiveSum(tmp, need, sums, base, W4);
    }

    // 3) scatter (origidx, valbits) into key-grouped storage
    scatter_kernel<<<GK512, 512>>>(samp, ridx, grad, rval, S, K, adj, cnt, base, z);

    // 4) per-word group sums (canonical origidx order) -> dense heads + histogram
    headsum2_kernel<<<(W4 + BLK - 1) / BLK, BLK>>>(cnt, base, z, hcur, hord, hkey, hist);

    // 5) threshold B (bin-granular, keeps all ties of the R-th element)
    coarse_kernel<<<1024, 256>>>(hist, super);
    select_kernel<<<1, 1024>>>(super, hist, (uint32_t)R, Bp);

    // 6) candidate filter over dense heads
    filter_kernel<<<(MAX_K + 511) / 512, 512>>>(hord, hkey, hcur, Bp, ccur, cord, ckey);

    // 7) sort candidates by ordkey
    {
        size_t need = 0;
        cub::DeviceRadixSort::SortPairs(nullptr, need, cord, sord, ckey, skey, M2, 0, 32);
        if (need <= TMPB)
            cub::DeviceRadixSort::SortPairs(tmp, need, cord, sord, ckey, skey, M2, 0, 32);
    }

    // 8) exact tie-break: ascending key within each equal-value run
    tiefix_kernel<<<(M2 + BLK - 1) / BLK, BLK>>>(sord, skey);

    // 9) emit [new_index (R,2), top_vals (R)] as f32
    int write_idx = 1, write_val = 1, val_off = 2 * R;
    if (out_size == R)          { write_idx = 0; val_off = 0; }
    else if (out_size == 2 * R) { write_val = 0; }
    output_kernel<<<(R + BLK - 1) / BLK, BLK>>>(sord, skey, R,
                                                write_idx, write_val, val_off,
                                                (float*)d_out);
}